// round 1
// baseline (speedup 1.0000x reference)
#include <cuda_runtime.h>
#include <math.h>
#include <stdint.h>

// ---------------- problem constants ----------------
#define BB 2
#define TT 4096
#define BT (BB*TT)          // 8192
#define DM 2048
#define NH 16
#define DK_ 128
#define DV_ 128
#define CH 64               // chunk
#define NC (TT/CH)          // 64 chunks
#define NVS 4               // dv splits in scan
#define WV (DV_/NVS)        // 32

// ---------------- scratch (device globals; no allocs) ----------------
__device__ float d_qpre[(size_t)BT*DM];
__device__ float d_kpre[(size_t)BT*DM];
__device__ float d_vpre[(size_t)BT*DM];
__device__ float d_q[(size_t)BT*DM];
__device__ float d_k[(size_t)BT*DM];
__device__ float d_v[(size_t)BT*DM];
__device__ float d_g[(size_t)BT*DM];
__device__ float d_gate[(size_t)BT*DM];
__device__ float d_glow[(size_t)BT*DK_];
__device__ float d_gatelow[(size_t)BT*DV_];
__device__ float d_betapre[(size_t)BT*NH];
__device__ float d_beta[(size_t)BT*NH];
__device__ float d_qt[(size_t)BT*DM];
__device__ float d_kt[(size_t)BT*DM];
__device__ float d_kd[(size_t)BT*DM];
__device__ float d_attn[(size_t)BB*NH*NC*CH*CH];
__device__ float d_tinv[(size_t)BB*NH*NC*CH*CH];
__device__ float d_dec[(size_t)BB*NH*NC*DK_];
__device__ float d_o[(size_t)BT*DM];
__device__ float d_og[(size_t)BT*DM];

// ---------------- generic fp32 tiled GEMM: C[M,N] = A[M,K] @ B[K,N] ----------------
// 128x128 block tile, BK=16, 256 threads, 8x8 per thread.
__global__ void gemm_kernel(const float* __restrict__ A, const float* __restrict__ B,
                            float* __restrict__ C, int M, int N, int K)
{
    __shared__ float As[16][132];
    __shared__ float Bs[16][132];
    const int bm = blockIdx.y * 128;
    const int bn = blockIdx.x * 128;
    const int tid = threadIdx.x;
    const int tr = tid >> 4;     // 0..15
    const int tc = tid & 15;     // 0..15

    float acc[8][8];
#pragma unroll
    for (int i = 0; i < 8; i++)
#pragma unroll
        for (int j = 0; j < 8; j++) acc[i][j] = 0.f;

    for (int k0 = 0; k0 < K; k0 += 16) {
        // load A tile (128 x 16): 512 float4, 2 per thread; store transposed
#pragma unroll
        for (int it = 0; it < 2; it++) {
            int lin = tid + it * 256;          // 0..511
            int m   = lin >> 2;                // 0..127
            int kq  = (lin & 3) * 4;           // 0,4,8,12
            float4 v = make_float4(0.f, 0.f, 0.f, 0.f);
            if (bm + m < M)
                v = *reinterpret_cast<const float4*>(&A[(size_t)(bm + m) * K + k0 + kq]);
            As[kq + 0][m] = v.x;
            As[kq + 1][m] = v.y;
            As[kq + 2][m] = v.z;
            As[kq + 3][m] = v.w;
        }
        // load B tile (16 x 128)
#pragma unroll
        for (int it = 0; it < 2; it++) {
            int lin = tid + it * 256;
            int kk  = lin >> 5;                // 0..15
            int nq  = (lin & 31) * 4;          // 0..124
            float4 v = make_float4(0.f, 0.f, 0.f, 0.f);
            if (bn + nq + 3 < N) {
                v = *reinterpret_cast<const float4*>(&B[(size_t)(k0 + kk) * N + bn + nq]);
            } else {
                float tmp[4] = {0.f, 0.f, 0.f, 0.f};
#pragma unroll
                for (int e = 0; e < 4; e++)
                    if (bn + nq + e < N) tmp[e] = B[(size_t)(k0 + kk) * N + bn + nq + e];
                v = make_float4(tmp[0], tmp[1], tmp[2], tmp[3]);
            }
            *reinterpret_cast<float4*>(&Bs[kk][nq]) = v;
        }
        __syncthreads();
#pragma unroll
        for (int kk = 0; kk < 16; kk++) {
            float4 a0 = *reinterpret_cast<float4*>(&As[kk][tr * 8]);
            float4 a1 = *reinterpret_cast<float4*>(&As[kk][tr * 8 + 4]);
            float4 b0 = *reinterpret_cast<float4*>(&Bs[kk][tc * 8]);
            float4 b1 = *reinterpret_cast<float4*>(&Bs[kk][tc * 8 + 4]);
            float ra[8] = {a0.x, a0.y, a0.z, a0.w, a1.x, a1.y, a1.z, a1.w};
            float rb[8] = {b0.x, b0.y, b0.z, b0.w, b1.x, b1.y, b1.z, b1.w};
#pragma unroll
            for (int i = 0; i < 8; i++)
#pragma unroll
                for (int j = 0; j < 8; j++) acc[i][j] += ra[i] * rb[j];
        }
        __syncthreads();
    }
    const int m0 = bm + tr * 8;
    const int n0 = bn + tc * 8;
#pragma unroll
    for (int i = 0; i < 8; i++) {
        if (m0 + i >= M) break;
#pragma unroll
        for (int j = 0; j < 8; j++)
            if (n0 + j < N) C[(size_t)(m0 + i) * N + n0 + j] = acc[i][j];
    }
}

// ---------------- causal depthwise conv (K=4) + silu (+ per-head l2norm) ----------------
__global__ void conv_silu_kernel(const float* __restrict__ pre, const float* __restrict__ w,
                                 float* __restrict__ out, int do_norm)
{
    __shared__ float ws[4];
    const int blk = blockIdx.x;               // (b*T + t)*NH + h
    const int h  = blk % NH;
    const int bt = blk / NH;
    const int t  = bt % TT;
    const int d  = threadIdx.x;               // 0..127
    const int c  = h * DK_ + d;

    float acc = 0.f;
#pragma unroll
    for (int j = 0; j < 4; j++) {
        int tt = t - 3 + j;
        if (tt >= 0) acc += w[c * 4 + j] * pre[(size_t)(bt - 3 + j) * DM + c];
    }
    float s = acc / (1.f + expf(-acc));       // silu
    if (do_norm) {
        float v = s * s;
#pragma unroll
        for (int o = 16; o > 0; o >>= 1) v += __shfl_down_sync(0xffffffffu, v, o);
        int lane = threadIdx.x & 31, wrp = threadIdx.x >> 5;
        if (lane == 0) ws[wrp] = v;
        __syncthreads();
        if (threadIdx.x == 0) ws[0] = ws[0] + ws[1] + ws[2] + ws[3];
        __syncthreads();
        float n = sqrtf(ws[0]);
        s = s / fmaxf(n, 1e-6f);
    }
    out[(size_t)bt * DM + c] = s;
}

// ---------------- elementwise ----------------
__global__ void gact_kernel(float* __restrict__ p, size_t n)
{
    size_t i = (size_t)blockIdx.x * blockDim.x + threadIdx.x;
    if (i < n) {
        float x = p[i];
        x = fminf(fmaxf(x, -10.f), 10.f);
        p[i] = -log1pf(expf(x));
    }
}
__global__ void sigmoid_kernel(float* __restrict__ p, size_t n)
{
    size_t i = (size_t)blockIdx.x * blockDim.x + threadIdx.x;
    if (i < n) p[i] = 1.f / (1.f + expf(-p[i]));
}
__global__ void sigclip_kernel(const float* __restrict__ src, float* __restrict__ dst, size_t n)
{
    size_t i = (size_t)blockIdx.x * blockDim.x + threadIdx.x;
    if (i < n) {
        float x = fminf(fmaxf(src[i], -10.f), 10.f);
        dst[i] = 1.f / (1.f + expf(-x));
    }
}

// ---------------- per-chunk prep ----------------
// grid = B*NH*NC blocks, 256 threads.
// computes: qt=q*e^cum, kt=k*e^cum, kd=k*e^(blast-cum), dec=e^blast,
//           attn = (qt @ kb^T) masked (incl), Tinv' = (I + diag(beta)*A)^-1 * diag(beta)
#define PREP_SMEM ((4*64*129 + 2*64*65 + 128 + 64) * 4)
__global__ void prep_kernel()
{
    extern __shared__ float sm[];
    float* s_cum = sm;                    // 64*129
    float* s_kt  = s_cum + 64 * 129;
    float* s_kb  = s_kt  + 64 * 129;
    float* s_qt  = s_kb  + 64 * 129;
    float* s_M   = s_qt  + 64 * 129;      // 64*65
    float* s_X   = s_M   + 64 * 65;       // 64*65
    float* s_bl  = s_X   + 64 * 65;       // 128
    float* s_be  = s_bl  + 128;           // 64

    const int blk = blockIdx.x;           // bh*NC + c
    const int c   = blk % NC;
    const int bh  = blk / NC;
    const int h   = bh % NH;
    const int b   = bh / NH;
    const int t0  = c * CH;
    const int tid = threadIdx.x;
    const size_t rowbase = (size_t)(b * TT + t0) * DM + h * DK_;

    // cumsum of g over chunk time
    if (tid < 128) {
        float run = 0.f;
        for (int t = 0; t < CH; t++) {
            run += d_g[rowbase + (size_t)t * DM + tid];
            s_cum[t * 129 + tid] = run;
        }
        s_bl[tid] = run;                  // cum at t=63
    }
    if (tid < 64) s_be[tid] = d_beta[(size_t)(b * TT + t0 + tid) * NH + h];
    __syncthreads();

    // materialize decayed tensors
    for (int idx = tid; idx < CH * 128; idx += 256) {
        int t = idx >> 7, d = idx & 127;
        float cum = s_cum[t * 129 + d];
        size_t gi = rowbase + (size_t)t * DM + d;
        float kv = d_k[gi];
        float qv = d_q[gi];
        float e  = expf(cum);
        float kt = kv * e;
        float qt = qv * e;
        float kb = kv * expf(-cum);
        float kd = kv * expf(s_bl[d] - cum);
        s_kt[t * 129 + d] = kt;
        s_qt[t * 129 + d] = qt;
        s_kb[t * 129 + d] = kb;
        d_kt[gi] = kt;
        d_qt[gi] = qt;
        d_kd[gi] = kd;
    }
    if (tid < 128) d_dec[(size_t)blk * 128 + tid] = expf(s_bl[tid]);
    __syncthreads();

    // A (strict-masked, beta-scaled) and attn (incl-masked): 4x4 per-thread tiles
    const size_t ab = (size_t)blk * (CH * CH);
    {
        const int tI = (tid >> 4) * 4;    // t block
        const int sI = (tid & 15) * 4;    // s block
        float a[4][4], at[4][4];
#pragma unroll
        for (int i = 0; i < 4; i++)
#pragma unroll
            for (int j = 0; j < 4; j++) { a[i][j] = 0.f; at[i][j] = 0.f; }
        for (int d = 0; d < 128; d++) {
            float kbv[4], ktv[4], qtv[4];
#pragma unroll
            for (int j = 0; j < 4; j++) kbv[j] = s_kb[(sI + j) * 129 + d];
#pragma unroll
            for (int i = 0; i < 4; i++) { ktv[i] = s_kt[(tI + i) * 129 + d]; qtv[i] = s_qt[(tI + i) * 129 + d]; }
#pragma unroll
            for (int i = 0; i < 4; i++)
#pragma unroll
                for (int j = 0; j < 4; j++) { a[i][j] += ktv[i] * kbv[j]; at[i][j] += qtv[i] * kbv[j]; }
        }
#pragma unroll
        for (int i = 0; i < 4; i++)
#pragma unroll
            for (int j = 0; j < 4; j++) {
                int t = tI + i, s = sI + j;
                s_M[t * 65 + s] = (s < t) ? s_be[t] * a[i][j] : 0.f;
                d_attn[ab + t * 64 + s] = (s <= t) ? at[i][j] : 0.f;
            }
    }
    __syncthreads();

    // Tinv = (I+M)^-1 via per-column forward substitution (columns independent)
    if (tid < 64) {
        const int j = tid;
        for (int i = 0; i < 64; i++) {
            float x = (i == j) ? 1.f : 0.f;
            for (int l = j; l < i; l++) x -= s_M[i * 65 + l] * s_X[l * 65 + j];
            s_X[i * 65 + j] = x;
        }
        float bj = s_be[j];
        for (int i = 0; i < 64; i++)
            d_tinv[ab + i * 64 + j] = s_X[i * 65 + j] * bj;
    }
}

// ---------------- sequential chunk scan ----------------
// grid = B*NH*NVS blocks (128), 256 threads, S[128 x WV] in smem.
#define SCAN_SMEM ((128*33 + 2*64*129 + 2*64*65 + 2*64*33) * 4)
__global__ void scan_kernel()
{
    extern __shared__ float sm[];
    float* sS  = sm;                      // 128*33
    float* sKT = sS  + 128 * 33;          // 64*129 (kt, later kd)
    float* sQT = sKT + 64 * 129;          // 64*129
    float* sAT = sQT + 64 * 129;          // 64*65
    float* sTI = sAT + 64 * 65;           // 64*65
    float* sRH = sTI + 64 * 65;           // 64*33 (v then rhs)
    float* sU  = sRH + 64 * 33;           // 64*33

    const int blk = blockIdx.x;           // bh*NVS + vb
    const int vb  = blk % NVS;
    const int bh  = blk / NVS;
    const int h   = bh % NH;
    const int b   = bh / NH;
    const int dv0 = vb * WV;
    const int tid = threadIdx.x;

    const int tr  = tid >> 4;             // 0..15 -> t base tr*4
    const int tcv = tid & 15;             // 0..15 -> v base tcv*2
    const int ur  = tid >> 3;             // 0..31 -> d base ur*4
    const int uc  = tid & 7;              // 0..7  -> v base uc*4

    for (int i = tid; i < 128 * 33; i += 256) sS[i] = 0.f;
    __syncthreads();

    for (int c = 0; c < NC; c++) {
        const int t0 = c * CH;
        const size_t rowbase = (size_t)(b * TT + t0) * DM + h * DK_;
        const size_t ab = (size_t)(bh * NC + c) * (CH * CH);

        // chunk loads
        for (int i = tid; i < CH * 128; i += 256) {
            int t = i >> 7, d = i & 127;
            size_t gi = rowbase + (size_t)t * DM + d;
            sKT[t * 129 + d] = d_kt[gi];
            sQT[t * 129 + d] = d_qt[gi];
        }
        for (int i = tid; i < CH * CH; i += 256) {
            int t = i >> 6, s = i & 63;
            sAT[t * 65 + s] = d_attn[ab + i];
            sTI[t * 65 + s] = d_tinv[ab + i];
        }
        for (int i = tid; i < CH * WV; i += 256) {
            int t = i >> 5, v = i & 31;
            sRH[t * 33 + v] = d_v[rowbase + (size_t)t * DM + dv0 + v];
        }
        __syncthreads();

        // phase b: rhs = v - kt @ S   (64x32, contract 128)
        {
            float acc[4][2] = {{0.f,0.f},{0.f,0.f},{0.f,0.f},{0.f,0.f}};
            for (int d = 0; d < 128; d++) {
                float kv[4];
#pragma unroll
                for (int i = 0; i < 4; i++) kv[i] = sKT[(tr * 4 + i) * 129 + d];
                float s0 = sS[d * 33 + tcv * 2 + 0];
                float s1 = sS[d * 33 + tcv * 2 + 1];
#pragma unroll
                for (int i = 0; i < 4; i++) { acc[i][0] += kv[i] * s0; acc[i][1] += kv[i] * s1; }
            }
#pragma unroll
            for (int i = 0; i < 4; i++) {
                sRH[(tr * 4 + i) * 33 + tcv * 2 + 0] -= acc[i][0];
                sRH[(tr * 4 + i) * 33 + tcv * 2 + 1] -= acc[i][1];
            }
        }
        __syncthreads();

        // load kd into sKT (kt consumed), overlapped with phase c
        for (int i = tid; i < CH * 128; i += 256) {
            int t = i >> 7, d = i & 127;
            sKT[t * 129 + d] = d_kd[rowbase + (size_t)t * DM + d];
        }
        // phase c: u = Tinv' @ rhs  (64x32, contract 64)
        {
            float acc[4][2] = {{0.f,0.f},{0.f,0.f},{0.f,0.f},{0.f,0.f}};
            for (int s = 0; s < 64; s++) {
                float tv[4];
#pragma unroll
                for (int i = 0; i < 4; i++) tv[i] = sTI[(tr * 4 + i) * 65 + s];
                float r0 = sRH[s * 33 + tcv * 2 + 0];
                float r1 = sRH[s * 33 + tcv * 2 + 1];
#pragma unroll
                for (int i = 0; i < 4; i++) { acc[i][0] += tv[i] * r0; acc[i][1] += tv[i] * r1; }
            }
#pragma unroll
            for (int i = 0; i < 4; i++) {
                sU[(tr * 4 + i) * 33 + tcv * 2 + 0] = acc[i][0];
                sU[(tr * 4 + i) * 33 + tcv * 2 + 1] = acc[i][1];
            }
        }
        __syncthreads();

        // phase d: o = qt @ S + attn @ u  -> global
        {
            float acc[4][2] = {{0.f,0.f},{0.f,0.f},{0.f,0.f},{0.f,0.f}};
            for (int d = 0; d < 128; d++) {
                float qv[4];
#pragma unroll
                for (int i = 0; i < 4; i++) qv[i] = sQT[(tr * 4 + i) * 129 + d];
                float s0 = sS[d * 33 + tcv * 2 + 0];
                float s1 = sS[d * 33 + tcv * 2 + 1];
#pragma unroll
                for (int i = 0; i < 4; i++) { acc[i][0] += qv[i] * s0; acc[i][1] += qv[i] * s1; }
            }
            for (int s = 0; s < 64; s++) {
                float av[4];
#pragma unroll
                for (int i = 0; i < 4; i++) av[i] = sAT[(tr * 4 + i) * 65 + s];
                float u0 = sU[s * 33 + tcv * 2 + 0];
                float u1 = sU[s * 33 + tcv * 2 + 1];
#pragma unroll
                for (int i = 0; i < 4; i++) { acc[i][0] += av[i] * u0; acc[i][1] += av[i] * u1; }
            }
#pragma unroll
            for (int i = 0; i < 4; i++) {
                size_t oi = rowbase + (size_t)(tr * 4 + i) * DM + dv0 + tcv * 2;
                d_o[oi + 0] = acc[i][0];
                d_o[oi + 1] = acc[i][1];
            }
        }
        __syncthreads();

        // phase e: S = dec * S + kd^T @ u  (128x32, contract 64)
        {
            float acc[4][4];
#pragma unroll
            for (int i = 0; i < 4; i++)
#pragma unroll
                for (int j = 0; j < 4; j++) acc[i][j] = 0.f;
            for (int t = 0; t < 64; t++) {
                float kv[4], uv[4];
#pragma unroll
                for (int i = 0; i < 4; i++) kv[i] = sKT[t * 129 + ur * 4 + i];
#pragma unroll
                for (int j = 0; j < 4; j++) uv[j] = sU[t * 33 + uc * 4 + j];
#pragma unroll
                for (int i = 0; i < 4; i++)
#pragma unroll
                    for (int j = 0; j < 4; j++) acc[i][j] += kv[i] * uv[j];
            }
            const size_t db = (size_t)(bh * NC + c) * 128;
#pragma unroll
            for (int i = 0; i < 4; i++) {
                int d = ur * 4 + i;
                float dc = d_dec[db + d];
#pragma unroll
                for (int j = 0; j < 4; j++) {
                    int v = uc * 4 + j;
                    sS[d * 33 + v] = dc * sS[d * 33 + v] + acc[i][j];
                }
            }
        }
        __syncthreads();
    }
}

// ---------------- rmsnorm * rms_w * gate ----------------
__global__ void rmsgate_kernel(const float* __restrict__ rmsw)
{
    __shared__ float ws[4];
    const int blk = blockIdx.x;           // bt*NH + h
    const int h  = blk % NH;
    const int bt = blk / NH;
    const int d  = threadIdx.x;
    const size_t idx = (size_t)bt * DM + h * DV_ + d;
    float val = d_o[idx];
    float v = val * val;
#pragma unroll
    for (int o = 16; o > 0; o >>= 1) v += __shfl_down_sync(0xffffffffu, v, o);
    int lane = threadIdx.x & 31, wrp = threadIdx.x >> 5;
    if (lane == 0) ws[wrp] = v;
    __syncthreads();
    if (threadIdx.x == 0) ws[0] = ws[0] + ws[1] + ws[2] + ws[3];
    __syncthreads();
    float ms = ws[0] * (1.f / 128.f);
    float scale = rsqrtf(ms + 1e-6f);
    d_og[idx] = val * scale * rmsw[d] * d_gate[idx];
}

// ---------------- host launch ----------------
static float* sym(const void* s) { void* p = nullptr; cudaGetSymbolAddress(&p, s); return (float*)p; }

extern "C" void kernel_launch(void* const* d_in, const int* in_sizes, int n_in,
                              void* d_out, int out_size)
{
    const float* x    = (const float*)d_in[0];
    const float* Wq   = (const float*)d_in[1];
    const float* Wk   = (const float*)d_in[2];
    const float* Wv   = (const float*)d_in[3];
    const float* Wo   = (const float*)d_in[4];
    const float* Wad  = (const float*)d_in[5];
    const float* Wau  = (const float*)d_in[6];
    const float* Wb   = (const float*)d_in[7];
    const float* Wgd  = (const float*)d_in[8];
    const float* Wgu  = (const float*)d_in[9];
    const float* cqw  = (const float*)d_in[10];
    const float* ckw  = (const float*)d_in[11];
    const float* cvw  = (const float*)d_in[12];
    const float* rmsw = (const float*)d_in[13];
    float* out = (float*)d_out;

    float* qpre    = sym(d_qpre);
    float* kpre    = sym(d_kpre);
    float* vpre    = sym(d_vpre);
    float* q_      = sym(d_q);
    float* k_      = sym(d_k);
    float* v_      = sym(d_v);
    float* g_      = sym(d_g);
    float* gate_   = sym(d_gate);
    float* glow    = sym(d_glow);
    float* gatelow = sym(d_gatelow);
    float* betapre = sym(d_betapre);
    float* beta_   = sym(d_beta);
    float* og_     = sym(d_og);

    cudaFuncSetAttribute((const void*)prep_kernel, cudaFuncAttributeMaxDynamicSharedMemorySize, PREP_SMEM);
    cudaFuncSetAttribute((const void*)scan_kernel, cudaFuncAttributeMaxDynamicSharedMemorySize, SCAN_SMEM);

    const dim3 gBig(DM / 128, BT / 128);      // N=2048
    const dim3 gLow(1, BT / 128);             // N<=128
    const dim3 blk256(256);

    // projections
    gemm_kernel<<<gBig, blk256>>>(x, Wq, qpre, BT, DM, DM);
    gemm_kernel<<<gBig, blk256>>>(x, Wk, kpre, BT, DM, DM);
    gemm_kernel<<<gBig, blk256>>>(x, Wv, vpre, BT, DM, DM);
    gemm_kernel<<<gLow, blk256>>>(x, Wad, glow, BT, DK_, DM);
    gemm_kernel<<<gBig, blk256>>>(glow, Wau, g_, BT, DM, DK_);
    gemm_kernel<<<gLow, blk256>>>(x, Wgd, gatelow, BT, DV_, DM);
    gemm_kernel<<<gBig, blk256>>>(gatelow, Wgu, gate_, BT, DM, DV_);
    gemm_kernel<<<gLow, blk256>>>(x, Wb, betapre, BT, NH, DM);

    // conv + silu (+ l2norm for q,k)
    conv_silu_kernel<<<BT * NH, 128>>>(qpre, cqw, q_, 1);
    conv_silu_kernel<<<BT * NH, 128>>>(kpre, ckw, k_, 1);
    conv_silu_kernel<<<BT * NH, 128>>>(vpre, cvw, v_, 0);

    // activations
    {
        size_t n = (size_t)BT * DM;
        int nb = (int)((n + 255) / 256);
        gact_kernel<<<nb, 256>>>(g_, n);
        sigmoid_kernel<<<nb, 256>>>(gate_, n);
        size_t nbeta = (size_t)BT * NH;
        sigclip_kernel<<<(int)((nbeta + 255) / 256), 256>>>(betapre, beta_, nbeta);
    }

    // per-chunk prep (parallel over all chunks)
    prep_kernel<<<BB * NH * NC, 256, PREP_SMEM>>>();

    // sequential scan (parallel over b,h,dv-split)
    scan_kernel<<<BB * NH * NVS, 256, SCAN_SMEM>>>();

    // rmsnorm + gate
    rmsgate_kernel<<<BT * NH, 128>>>(rmsw);

    // output projection
    gemm_kernel<<<gBig, blk256>>>(og_, Wo, out, BT, DM, DM);
}

// round 3
// speedup vs baseline: 2.0448x; 2.0448x over previous
#include <cuda_runtime.h>
#include <math.h>
#include <stdint.h>

// ---------------- problem constants ----------------
#define BB 2
#define TT 4096
#define BT (BB*TT)          // 8192
#define DM 2048
#define NH 16
#define DK_ 128
#define DV_ 128
#define CH 64               // chunk
#define NC (TT/CH)          // 64 chunks
#define NVS 4               // dv splits in scan
#define WV (DV_/NVS)        // 32

// ---------------- scratch (device globals; no allocs) ----------------
__device__ float d_qpre[(size_t)BT*DM];
__device__ float d_kpre[(size_t)BT*DM];
__device__ float d_vpre[(size_t)BT*DM];
__device__ float d_q[(size_t)BT*DM];
__device__ float d_k[(size_t)BT*DM];
__device__ float d_v[(size_t)BT*DM];
__device__ float d_g[(size_t)BT*DM];
__device__ float d_gate[(size_t)BT*DM];
__device__ float d_glow[(size_t)BT*DK_];
__device__ float d_gatelow[(size_t)BT*DV_];
__device__ float d_beta[(size_t)BT*NH];
__device__ float d_qt[(size_t)BT*DM];
__device__ float d_kt[(size_t)BT*DM];
__device__ float d_kd[(size_t)BT*DM];
__device__ float d_attn[(size_t)BB*NH*NC*CH*CH];
__device__ float d_tinv[(size_t)BB*NH*NC*CH*CH];
__device__ float d_dec[(size_t)BB*NH*NC*DK_];
__device__ float d_o[(size_t)BT*DM];
__device__ float d_og[(size_t)BT*DM];

// ---------------- tf32 helpers ----------------
__device__ __forceinline__ uint32_t f2tf32(float x)
{
    uint32_t y;
    asm("cvt.rna.tf32.f32 %0, %1;" : "=r"(y) : "f"(x));
    return y;
}

__device__ __forceinline__ void mma_tf32(float* c, const uint32_t* a, const uint32_t* b)
{
    asm volatile(
        "mma.sync.aligned.m16n8k8.row.col.f32.tf32.tf32.f32 "
        "{%0,%1,%2,%3}, {%4,%5,%6,%7}, {%8,%9}, {%0,%1,%2,%3};"
        : "+f"(c[0]), "+f"(c[1]), "+f"(c[2]), "+f"(c[3])
        : "r"(a[0]), "r"(a[1]), "r"(a[2]), "r"(a[3]), "r"(b[0]), "r"(b[1]));
}

// ---------------- tf32 tensor-core GEMM: C[M,N] = A[M,K] @ B[K,N] ----------------
// BM x 128 block tile, BK=16, 256 threads (8 warps), warp tile (BM/2) x 32.
// Requires M%BM==0, N%128==0, K%16==0 (true for all call sites).
template<int BM>
__global__ void __launch_bounds__(256) gemm_tf32(const float* __restrict__ A,
                                                 const float* __restrict__ Bm,
                                                 float* __restrict__ C,
                                                 int M, int N, int K)
{
    constexpr int MT = BM / 32;          // m16 tiles per warp
    constexpr int ASD = BM + 8;          // padded strides -> conflict-free frag loads
    constexpr int BSD = 128 + 8;
    __shared__ uint32_t As[16][ASD];
    __shared__ uint32_t Bs[16][BSD];

    const int bm = blockIdx.y * BM;
    const int bn = blockIdx.x * 128;
    const int tid  = threadIdx.x;
    const int lane = tid & 31;
    const int wid  = tid >> 5;
    const int wm = (wid >> 2) * (BM / 2);
    const int wn = (wid & 3) * 32;

    constexpr int ALD = (BM * 16) / (4 * 256);   // float4 A loads per thread (2 or 1)
    float4 ra[ALD], rb[2];

    float acc[MT][4][4];
#pragma unroll
    for (int mt = 0; mt < MT; mt++)
#pragma unroll
        for (int nt = 0; nt < 4; nt++)
#pragma unroll
            for (int e = 0; e < 4; e++) acc[mt][nt][e] = 0.f;

    auto ldG = [&](int k0) {
#pragma unroll
        for (int i = 0; i < ALD; i++) {
            int lin = tid + i * 256;
            int m = lin >> 2, kq = (lin & 3) * 4;
            ra[i] = *reinterpret_cast<const float4*>(&A[(size_t)(bm + m) * K + k0 + kq]);
        }
#pragma unroll
        for (int i = 0; i < 2; i++) {
            int lin = tid + i * 256;
            int kk = lin >> 5, nq = (lin & 31) * 4;
            rb[i] = *reinterpret_cast<const float4*>(&Bm[(size_t)(k0 + kk) * N + bn + nq]);
        }
    };
    auto stS = [&]() {
#pragma unroll
        for (int i = 0; i < ALD; i++) {
            int lin = tid + i * 256;
            int m = lin >> 2, kq = (lin & 3) * 4;
            As[kq + 0][m] = f2tf32(ra[i].x);
            As[kq + 1][m] = f2tf32(ra[i].y);
            As[kq + 2][m] = f2tf32(ra[i].z);
            As[kq + 3][m] = f2tf32(ra[i].w);
        }
#pragma unroll
        for (int i = 0; i < 2; i++) {
            int lin = tid + i * 256;
            int kk = lin >> 5, nq = (lin & 31) * 4;
            Bs[kk][nq + 0] = f2tf32(rb[i].x);
            Bs[kk][nq + 1] = f2tf32(rb[i].y);
            Bs[kk][nq + 2] = f2tf32(rb[i].z);
            Bs[kk][nq + 3] = f2tf32(rb[i].w);
        }
    };

    ldG(0);
    stS();
    __syncthreads();

    for (int k0 = 0; k0 < K; k0 += 16) {
        const bool nxt = (k0 + 16) < K;
        if (nxt) ldG(k0 + 16);           // overlap global loads with compute
#pragma unroll
        for (int ks = 0; ks < 16; ks += 8) {
            uint32_t af[MT][4];
#pragma unroll
            for (int mt = 0; mt < MT; mt++) {
                int r  = wm + mt * 16 + (lane >> 2);
                int kc = ks + (lane & 3);
                af[mt][0] = As[kc][r];
                af[mt][1] = As[kc][r + 8];
                af[mt][2] = As[kc + 4][r];
                af[mt][3] = As[kc + 4][r + 8];
            }
            uint32_t bf[4][2];
#pragma unroll
            for (int nt = 0; nt < 4; nt++) {
                int cN = wn + nt * 8 + (lane >> 2);
                int kc = ks + (lane & 3);
                bf[nt][0] = Bs[kc][cN];
                bf[nt][1] = Bs[kc + 4][cN];
            }
#pragma unroll
            for (int mt = 0; mt < MT; mt++)
#pragma unroll
                for (int nt = 0; nt < 4; nt++)
                    mma_tf32(acc[mt][nt], af[mt], bf[nt]);
        }
        __syncthreads();
        if (nxt) { stS(); __syncthreads(); }
    }

#pragma unroll
    for (int mt = 0; mt < MT; mt++) {
        int r0 = bm + wm + mt * 16 + (lane >> 2);
#pragma unroll
        for (int nt = 0; nt < 4; nt++) {
            int c0 = bn + wn + nt * 8 + (lane & 3) * 2;
            *reinterpret_cast<float2*>(&C[(size_t)r0 * N + c0]) =
                make_float2(acc[mt][nt][0], acc[mt][nt][1]);
            *reinterpret_cast<float2*>(&C[(size_t)(r0 + 8) * N + c0]) =
                make_float2(acc[mt][nt][2], acc[mt][nt][3]);
        }
    }
}

// ---------------- fused beta = sigmoid(clip(x @ Wb)) ----------------
// 8 warps/block, warp per row; Wb slice staged in smem. fp32-exact.
__global__ void beta_kernel(const float* __restrict__ x, const float* __restrict__ Wb,
                            float* __restrict__ beta)
{
    __shared__ float wbs[256][17];
    const int tid  = threadIdx.x;
    const int lane = tid & 31;
    const int wid  = tid >> 5;
    const int row  = blockIdx.x * 8 + wid;

    float acc[16];
#pragma unroll
    for (int c = 0; c < 16; c++) acc[c] = 0.f;

    for (int k0 = 0; k0 < DM; k0 += 256) {
        __syncthreads();
        {
            const float* src = &Wb[(size_t)(k0 + tid) * 16];
#pragma unroll
            for (int c = 0; c < 16; c++) wbs[tid][c] = src[c];
        }
        __syncthreads();
#pragma unroll
        for (int k8 = 0; k8 < 8; k8++) {
            float xv = x[(size_t)row * DM + k0 + k8 * 32 + lane];
#pragma unroll
            for (int c = 0; c < 16; c++) acc[c] += xv * wbs[k8 * 32 + lane][c];
        }
    }
#pragma unroll
    for (int c = 0; c < 16; c++) {
#pragma unroll
        for (int off = 16; off; off >>= 1)
            acc[c] += __shfl_xor_sync(0xffffffffu, acc[c], off);
    }
    if (lane == 0) {
#pragma unroll
        for (int c = 0; c < 16; c++) {
            float v = fminf(fmaxf(acc[c], -10.f), 10.f);
            beta[(size_t)row * 16 + c] = 1.f / (1.f + expf(-v));
        }
    }
}

// ---------------- causal depthwise conv (K=4) + silu (+ per-head l2norm) ----------------
__global__ void conv_silu_kernel(const float* __restrict__ pre, const float* __restrict__ w,
                                 float* __restrict__ out, int do_norm)
{
    __shared__ float ws[4];
    const int blk = blockIdx.x;               // (b*T + t)*NH + h
    const int h  = blk % NH;
    const int bt = blk / NH;
    const int t  = bt % TT;
    const int d  = threadIdx.x;               // 0..127
    const int c  = h * DK_ + d;

    float acc = 0.f;
#pragma unroll
    for (int j = 0; j < 4; j++) {
        int tt = t - 3 + j;
        if (tt >= 0) acc += w[c * 4 + j] * pre[(size_t)(bt - 3 + j) * DM + c];
    }
    float s = acc / (1.f + expf(-acc));       // silu
    if (do_norm) {
        float v = s * s;
#pragma unroll
        for (int o = 16; o > 0; o >>= 1) v += __shfl_down_sync(0xffffffffu, v, o);
        int lane = threadIdx.x & 31, wrp = threadIdx.x >> 5;
        if (lane == 0) ws[wrp] = v;
        __syncthreads();
        if (threadIdx.x == 0) ws[0] = ws[0] + ws[1] + ws[2] + ws[3];
        __syncthreads();
        float n = sqrtf(ws[0]);
        s = s / fmaxf(n, 1e-6f);
    }
    out[(size_t)bt * DM + c] = s;
}

// ---------------- elementwise ----------------
__global__ void gact_kernel(float* __restrict__ p, size_t n)
{
    size_t i = (size_t)blockIdx.x * blockDim.x + threadIdx.x;
    if (i < n) {
        float x = p[i];
        x = fminf(fmaxf(x, -10.f), 10.f);
        p[i] = -log1pf(expf(x));
    }
}
__global__ void sigmoid_kernel(float* __restrict__ p, size_t n)
{
    size_t i = (size_t)blockIdx.x * blockDim.x + threadIdx.x;
    if (i < n) p[i] = 1.f / (1.f + expf(-p[i]));
}

// ---------------- per-chunk prep ----------------
#define PREP_SMEM ((4*64*129 + 2*64*65 + 128 + 64) * 4)
__global__ void prep_kernel()
{
    extern __shared__ float sm[];
    float* s_cum = sm;                    // 64*129
    float* s_kt  = s_cum + 64 * 129;
    float* s_kb  = s_kt  + 64 * 129;
    float* s_qt  = s_kb  + 64 * 129;
    float* s_M   = s_qt  + 64 * 129;      // 64*65
    float* s_X   = s_M   + 64 * 65;       // 64*65
    float* s_bl  = s_X   + 64 * 65;       // 128
    float* s_be  = s_bl  + 128;           // 64

    const int blk = blockIdx.x;           // bh*NC + c
    const int c   = blk % NC;
    const int bh  = blk / NC;
    const int h   = bh % NH;
    const int b   = bh / NH;
    const int t0  = c * CH;
    const int tid = threadIdx.x;
    const size_t rowbase = (size_t)(b * TT + t0) * DM + h * DK_;

    if (tid < 128) {
        float run = 0.f;
        for (int t = 0; t < CH; t++) {
            run += d_g[rowbase + (size_t)t * DM + tid];
            s_cum[t * 129 + tid] = run;
        }
        s_bl[tid] = run;
    }
    if (tid < 64) s_be[tid] = d_beta[(size_t)(b * TT + t0 + tid) * NH + h];
    __syncthreads();

    for (int idx = tid; idx < CH * 128; idx += 256) {
        int t = idx >> 7, d = idx & 127;
        float cum = s_cum[t * 129 + d];
        size_t gi = rowbase + (size_t)t * DM + d;
        float kv = d_k[gi];
        float qv = d_q[gi];
        float e  = expf(cum);
        float kt = kv * e;
        float qt = qv * e;
        float kb = kv * expf(-cum);
        float kd = kv * expf(s_bl[d] - cum);
        s_kt[t * 129 + d] = kt;
        s_qt[t * 129 + d] = qt;
        s_kb[t * 129 + d] = kb;
        d_kt[gi] = kt;
        d_qt[gi] = qt;
        d_kd[gi] = kd;
    }
    if (tid < 128) d_dec[(size_t)blk * 128 + tid] = expf(s_bl[tid]);
    __syncthreads();

    const size_t ab = (size_t)blk * (CH * CH);
    {
        const int tI = (tid >> 4) * 4;
        const int sI = (tid & 15) * 4;
        float a[4][4], at[4][4];
#pragma unroll
        for (int i = 0; i < 4; i++)
#pragma unroll
            for (int j = 0; j < 4; j++) { a[i][j] = 0.f; at[i][j] = 0.f; }
        for (int d = 0; d < 128; d++) {
            float kbv[4], ktv[4], qtv[4];
#pragma unroll
            for (int j = 0; j < 4; j++) kbv[j] = s_kb[(sI + j) * 129 + d];
#pragma unroll
            for (int i = 0; i < 4; i++) { ktv[i] = s_kt[(tI + i) * 129 + d]; qtv[i] = s_qt[(tI + i) * 129 + d]; }
#pragma unroll
            for (int i = 0; i < 4; i++)
#pragma unroll
                for (int j = 0; j < 4; j++) { a[i][j] += ktv[i] * kbv[j]; at[i][j] += qtv[i] * kbv[j]; }
        }
#pragma unroll
        for (int i = 0; i < 4; i++)
#pragma unroll
            for (int j = 0; j < 4; j++) {
                int t = tI + i, s = sI + j;
                s_M[t * 65 + s] = (s < t) ? s_be[t] * a[i][j] : 0.f;
                d_attn[ab + t * 64 + s] = (s <= t) ? at[i][j] : 0.f;
            }
    }
    __syncthreads();

    if (tid < 64) {
        const int j = tid;
        for (int i = 0; i < 64; i++) {
            float x = (i == j) ? 1.f : 0.f;
            for (int l = j; l < i; l++) x -= s_M[i * 65 + l] * s_X[l * 65 + j];
            s_X[i * 65 + j] = x;
        }
        float bj = s_be[j];
        for (int i = 0; i < 64; i++)
            d_tinv[ab + i * 64 + j] = s_X[i * 65 + j] * bj;
    }
}

// ---------------- sequential chunk scan ----------------
#define SCAN_SMEM ((128*33 + 2*64*129 + 2*64*65 + 2*64*33) * 4)
__global__ void scan_kernel()
{
    extern __shared__ float sm[];
    float* sS  = sm;                      // 128*33
    float* sKT = sS  + 128 * 33;          // 64*129 (kt, later kd)
    float* sQT = sKT + 64 * 129;          // 64*129
    float* sAT = sQT + 64 * 129;          // 64*65
    float* sTI = sAT + 64 * 65;           // 64*65
    float* sRH = sTI + 64 * 65;           // 64*33 (v then rhs)
    float* sU  = sRH + 64 * 33;           // 64*33

    const int blk = blockIdx.x;           // bh*NVS + vb
    const int vb  = blk % NVS;
    const int bh  = blk / NVS;
    const int h   = bh % NH;
    const int b   = bh / NH;
    const int dv0 = vb * WV;
    const int tid = threadIdx.x;

    const int tr  = tid >> 4;
    const int tcv = tid & 15;
    const int ur  = tid >> 3;
    const int uc  = tid & 7;

    for (int i = tid; i < 128 * 33; i += 256) sS[i] = 0.f;
    __syncthreads();

    for (int c = 0; c < NC; c++) {
        const int t0 = c * CH;
        const size_t rowbase = (size_t)(b * TT + t0) * DM + h * DK_;
        const size_t ab = (size_t)(bh * NC + c) * (CH * CH);

        for (int i = tid; i < CH * 128; i += 256) {
            int t = i >> 7, d = i & 127;
            size_t gi = rowbase + (size_t)t * DM + d;
            sKT[t * 129 + d] = d_kt[gi];
            sQT[t * 129 + d] = d_qt[gi];
        }
        for (int i = tid; i < CH * CH; i += 256) {
            int t = i >> 6, s = i & 63;
            sAT[t * 65 + s] = d_attn[ab + i];
            sTI[t * 65 + s] = d_tinv[ab + i];
        }
        for (int i = tid; i < CH * WV; i += 256) {
            int t = i >> 5, v = i & 31;
            sRH[t * 33 + v] = d_v[rowbase + (size_t)t * DM + dv0 + v];
        }
        __syncthreads();

        // rhs = v - kt @ S
        {
            float acc[4][2] = {{0.f,0.f},{0.f,0.f},{0.f,0.f},{0.f,0.f}};
            for (int d = 0; d < 128; d++) {
                float kv[4];
#pragma unroll
                for (int i = 0; i < 4; i++) kv[i] = sKT[(tr * 4 + i) * 129 + d];
                float s0 = sS[d * 33 + tcv * 2 + 0];
                float s1 = sS[d * 33 + tcv * 2 + 1];
#pragma unroll
                for (int i = 0; i < 4; i++) { acc[i][0] += kv[i] * s0; acc[i][1] += kv[i] * s1; }
            }
#pragma unroll
            for (int i = 0; i < 4; i++) {
                sRH[(tr * 4 + i) * 33 + tcv * 2 + 0] -= acc[i][0];
                sRH[(tr * 4 + i) * 33 + tcv * 2 + 1] -= acc[i][1];
            }
        }
        __syncthreads();

        for (int i = tid; i < CH * 128; i += 256) {
            int t = i >> 7, d = i & 127;
            sKT[t * 129 + d] = d_kd[rowbase + (size_t)t * DM + d];
        }
        // u = Tinv' @ rhs
        {
            float acc[4][2] = {{0.f,0.f},{0.f,0.f},{0.f,0.f},{0.f,0.f}};
            for (int s = 0; s < 64; s++) {
                float tv[4];
#pragma unroll
                for (int i = 0; i < 4; i++) tv[i] = sTI[(tr * 4 + i) * 65 + s];
                float r0 = sRH[s * 33 + tcv * 2 + 0];
                float r1 = sRH[s * 33 + tcv * 2 + 1];
#pragma unroll
                for (int i = 0; i < 4; i++) { acc[i][0] += tv[i] * r0; acc[i][1] += tv[i] * r1; }
            }
#pragma unroll
            for (int i = 0; i < 4; i++) {
                sU[(tr * 4 + i) * 33 + tcv * 2 + 0] = acc[i][0];
                sU[(tr * 4 + i) * 33 + tcv * 2 + 1] = acc[i][1];
            }
        }
        __syncthreads();

        // o = qt @ S + attn @ u
        {
            float acc[4][2] = {{0.f,0.f},{0.f,0.f},{0.f,0.f},{0.f,0.f}};
            for (int d = 0; d < 128; d++) {
                float qv[4];
#pragma unroll
                for (int i = 0; i < 4; i++) qv[i] = sQT[(tr * 4 + i) * 129 + d];
                float s0 = sS[d * 33 + tcv * 2 + 0];
                float s1 = sS[d * 33 + tcv * 2 + 1];
#pragma unroll
                for (int i = 0; i < 4; i++) { acc[i][0] += qv[i] * s0; acc[i][1] += qv[i] * s1; }
            }
            for (int s = 0; s < 64; s++) {
                float av[4];
#pragma unroll
                for (int i = 0; i < 4; i++) av[i] = sAT[(tr * 4 + i) * 65 + s];
                float u0 = sU[s * 33 + tcv * 2 + 0];
                float u1 = sU[s * 33 + tcv * 2 + 1];
#pragma unroll
                for (int i = 0; i < 4; i++) { acc[i][0] += av[i] * u0; acc[i][1] += av[i] * u1; }
            }
#pragma unroll
            for (int i = 0; i < 4; i++) {
                size_t oi = rowbase + (size_t)(tr * 4 + i) * DM + dv0 + tcv * 2;
                d_o[oi + 0] = acc[i][0];
                d_o[oi + 1] = acc[i][1];
            }
        }
        __syncthreads();

        // S = dec * S + kd^T @ u
        {
            float acc[4][4];
#pragma unroll
            for (int i = 0; i < 4; i++)
#pragma unroll
                for (int j = 0; j < 4; j++) acc[i][j] = 0.f;
            for (int t = 0; t < 64; t++) {
                float kv[4], uv[4];
#pragma unroll
                for (int i = 0; i < 4; i++) kv[i] = sKT[t * 129 + ur * 4 + i];
#pragma unroll
                for (int j = 0; j < 4; j++) uv[j] = sU[t * 33 + uc * 4 + j];
#pragma unroll
                for (int i = 0; i < 4; i++)
#pragma unroll
                    for (int j = 0; j < 4; j++) acc[i][j] += kv[i] * uv[j];
            }
            const size_t db = (size_t)(bh * NC + c) * 128;
#pragma unroll
            for (int i = 0; i < 4; i++) {
                int d = ur * 4 + i;
                float dc = d_dec[db + d];
#pragma unroll
                for (int j = 0; j < 4; j++) {
                    int v = uc * 4 + j;
                    sS[d * 33 + v] = dc * sS[d * 33 + v] + acc[i][j];
                }
            }
        }
        __syncthreads();
    }
}

// ---------------- rmsnorm * rms_w * gate ----------------
__global__ void rmsgate_kernel(const float* __restrict__ rmsw)
{
    __shared__ float ws[4];
    const int blk = blockIdx.x;           // bt*NH + h
    const int h  = blk % NH;
    const int bt = blk / NH;
    const int d  = threadIdx.x;
    const size_t idx = (size_t)bt * DM + h * DV_ + d;
    float val = d_o[idx];
    float v = val * val;
#pragma unroll
    for (int o = 16; o > 0; o >>= 1) v += __shfl_down_sync(0xffffffffu, v, o);
    int lane = threadIdx.x & 31, wrp = threadIdx.x >> 5;
    if (lane == 0) ws[wrp] = v;
    __syncthreads();
    if (threadIdx.x == 0) ws[0] = ws[0] + ws[1] + ws[2] + ws[3];
    __syncthreads();
    float ms = ws[0] * (1.f / 128.f);
    float scale = rsqrtf(ms + 1e-6f);
    d_og[idx] = val * scale * rmsw[d] * d_gate[idx];
}

// ---------------- host launch ----------------
static float* sym(const void* s) { void* p = nullptr; cudaGetSymbolAddress(&p, s); return (float*)p; }

extern "C" void kernel_launch(void* const* d_in, const int* in_sizes, int n_in,
                              void* d_out, int out_size)
{
    const float* x    = (const float*)d_in[0];
    const float* Wq   = (const float*)d_in[1];
    const float* Wk   = (const float*)d_in[2];
    const float* Wv   = (const float*)d_in[3];
    const float* Wo   = (const float*)d_in[4];
    const float* Wad  = (const float*)d_in[5];
    const float* Wau  = (const float*)d_in[6];
    const float* Wb   = (const float*)d_in[7];
    const float* Wgd  = (const float*)d_in[8];
    const float* Wgu  = (const float*)d_in[9];
    const float* cqw  = (const float*)d_in[10];
    const float* ckw  = (const float*)d_in[11];
    const float* cvw  = (const float*)d_in[12];
    const float* rmsw = (const float*)d_in[13];
    float* out = (float*)d_out;

    float* qpre    = sym(d_qpre);
    float* kpre    = sym(d_kpre);
    float* vpre    = sym(d_vpre);
    float* q_      = sym(d_q);
    float* k_      = sym(d_k);
    float* v_      = sym(d_v);
    float* g_      = sym(d_g);
    float* gate_   = sym(d_gate);
    float* glow    = sym(d_glow);
    float* gatelow = sym(d_gatelow);
    float* beta_   = sym(d_beta);
    float* og_     = sym(d_og);

    cudaFuncSetAttribute((const void*)prep_kernel, cudaFuncAttributeMaxDynamicSharedMemorySize, PREP_SMEM);
    cudaFuncSetAttribute((const void*)scan_kernel, cudaFuncAttributeMaxDynamicSharedMemorySize, SCAN_SMEM);

    const dim3 gBig(DM / 128, BT / 128);      // (16, 64)
    const dim3 gLowA(1, BT / 64);             // (1, 128) for BM=64, N=128
    const dim3 blk256(256);

    // low-rank down-projections + beta first (so ncu capture slot 5 = big GEMM)
    gemm_tf32<64><<<gLowA, blk256>>>(x, Wad, glow, BT, DK_, DM);       // 0
    gemm_tf32<64><<<gLowA, blk256>>>(x, Wgd, gatelow, BT, DV_, DM);    // 1
    beta_kernel<<<BT / 8, blk256>>>(x, Wb, beta_);                     // 2

    // big projections
    gemm_tf32<128><<<gBig, blk256>>>(x, Wq, qpre, BT, DM, DM);         // 3
    gemm_tf32<128><<<gBig, blk256>>>(x, Wk, kpre, BT, DM, DM);         // 4
    gemm_tf32<128><<<gBig, blk256>>>(x, Wv, vpre, BT, DM, DM);         // 5 <- ncu capture
    gemm_tf32<128><<<gBig, blk256>>>(glow, Wau, g_, BT, DM, DK_);      // 6
    gemm_tf32<128><<<gBig, blk256>>>(gatelow, Wgu, gate_, BT, DM, DV_);// 7

    // conv + silu (+ l2norm for q,k)
    conv_silu_kernel<<<BT * NH, 128>>>(qpre, cqw, q_, 1);
    conv_silu_kernel<<<BT * NH, 128>>>(kpre, ckw, k_, 1);
    conv_silu_kernel<<<BT * NH, 128>>>(vpre, cvw, v_, 0);

    // activations
    {
        size_t n = (size_t)BT * DM;
        int nb = (int)((n + 255) / 256);
        gact_kernel<<<nb, 256>>>(g_, n);
        sigmoid_kernel<<<nb, 256>>>(gate_, n);
    }

    // per-chunk prep (parallel over all chunks)
    prep_kernel<<<BB * NH * NC, 256, PREP_SMEM>>>();

    // sequential scan (parallel over b,h,dv-split)
    scan_kernel<<<BB * NH * NVS, 256, SCAN_SMEM>>>();

    // rmsnorm + gate
    rmsgate_kernel<<<BT * NH, 128>>>(rmsw);

    // output projection
    gemm_tf32<128><<<gBig, blk256>>>(og_, Wo, out, BT, DM, DM);
}